// round 1
// baseline (speedup 1.0000x reference)
#include <cuda_runtime.h>

// filtfilt with 2nd-order Butterworth, zero initial state, odd extension padlen=9.
// 1024 rows x 32768 samples. Normalization by max|x| cancels exactly (linear filter),
// so it is omitted. Sequential IIR parallelized via warm-up truncation:
// poles at |z|=0.577 -> 0.577^32 = 2.3e-8 truncation error << 1e-3 tolerance.

#define T_THREADS 64
#define CHUNK_C   64
#define S_OUT     (T_THREADS * CHUNK_C)   // 4096 outputs per block
#define W_WARM    32
#define PADLEN    9
#define N_SAMP    32768
#define E_LEN     (N_SAMP + 2 * PADLEN)   // 32786 extended length
#define N_CHUNKS  (N_SAMP / S_OUT)        // 8

#define E_MAX   (S_OUT + 2 * W_WARM)              // 4160
#define Y1_MAX  (S_OUT + W_WARM)                  // 4128
#define E_PAD   (E_MAX + (E_MAX >> 6) + 1)        // padded smem sizes
#define Y1_PAD  (Y1_MAX + (Y1_MAX >> 6) + 1)

__device__ __forceinline__ int padidx(int i) { return i + (i >> 6); }

__global__ void __launch_bounds__(T_THREADS)
filtfilt_kernel(const float* __restrict__ x, float* __restrict__ out)
{
    extern __shared__ float sm[];
    float* e_s  = sm;          // extended input, later reused for y2 staging
    float* y1_s = sm + E_PAD;  // forward-pass output

    const int row   = blockIdx.y;
    const int chunk = blockIdx.x;
    const int tid   = threadIdx.x;

    const float* xr   = x   + (long)row * N_SAMP;
    float*       outr = out + (long)row * N_SAMP;

    const int t0   = PADLEN + chunk * S_OUT;              // first output (e-space)
    const int e_lo = max(0, t0 - W_WARM);
    const int e_hi = min(t0 + S_OUT + W_WARM, E_LEN);
    const int e_cnt = e_hi - e_lo;

    // normalized coefficients (a0 = 1)
    const float b0 = 0.0976310729378175f;
    const float b1 = 0.195262145875635f;
    const float b2 = 0.0976310729378175f;
    const float a1 = -0.9428090415820634f;
    const float a2 = 0.33333333333333337f;

    // ---- stage extended signal (odd extension computed on the fly) ----
    for (int i = tid; i < e_cnt; i += T_THREADS) {
        int t = e_lo + i;
        float v;
        if (t >= PADLEN) {
            if (t < PADLEN + N_SAMP)
                v = xr[t - PADLEN];
            else  // right odd extension: 2*x[N-1] - x[N-2-j]
                v = 2.0f * xr[N_SAMP - 1] - xr[2 * N_SAMP + PADLEN - 2 - t];
        } else {  // left odd extension: 2*x[0] - x[PADLEN - t]
            v = 2.0f * xr[0] - xr[PADLEN - t];
        }
        e_s[padidx(i)] = v;
    }
    __syncthreads();

    // ---- forward IIR (transposed DF-II), per-thread chunk with warm-up ----
    {
        const int u      = t0 + tid * CHUNK_C;
        const int wstart = max(e_lo, u - W_WARM);
        int kend = u + CHUNK_C;
        if (tid == T_THREADS - 1)  // last thread also computes the +W extension
            kend = min(u + CHUNK_C + W_WARM, E_LEN);

        float z1 = 0.0f, z2 = 0.0f;
        #pragma unroll 4
        for (int t = wstart; t < u; ++t) {          // warm-up (discarded)
            float ev = e_s[padidx(t - e_lo)];
            float y  = fmaf(b0, ev, z1);
            z1 = fmaf(b1, ev, fmaf(-a1, y, z2));
            z2 = fmaf(b2, ev, -a2 * y);
        }
        #pragma unroll 4
        for (int t = u; t < kend; ++t) {            // kept region
            float ev = e_s[padidx(t - e_lo)];
            float y  = fmaf(b0, ev, z1);
            z1 = fmaf(b1, ev, fmaf(-a1, y, z2));
            z2 = fmaf(b2, ev, -a2 * y);
            y1_s[padidx(t - t0)] = y;
        }
    }
    __syncthreads();

    // ---- backward IIR on y1, per-thread chunk with warm-up ----
    {
        const int u      = t0 + tid * CHUNK_C;
        const int bstart = min(u + CHUNK_C + W_WARM, E_LEN) - 1;  // exact at true end

        float z1 = 0.0f, z2 = 0.0f;
        #pragma unroll 4
        for (int t = bstart; t >= u + CHUNK_C; --t) {  // warm-up (discarded)
            float v = y1_s[padidx(t - t0)];
            float y = fmaf(b0, v, z1);
            z1 = fmaf(b1, v, fmaf(-a1, y, z2));
            z2 = fmaf(b2, v, -a2 * y);
        }
        #pragma unroll 4
        for (int t = u + CHUNK_C - 1; t >= u; --t) {   // kept region -> stage in e_s
            float v = y1_s[padidx(t - t0)];
            float y = fmaf(b0, v, z1);
            z1 = fmaf(b1, v, fmaf(-a1, y, z2));
            z2 = fmaf(b2, v, -a2 * y);
            e_s[padidx(t - t0)] = y;
        }
    }
    __syncthreads();

    // ---- coalesced writeout ----
    for (int i = tid; i < S_OUT; i += T_THREADS) {
        outr[t0 - PADLEN + i] = e_s[padidx(i)];
    }
}

extern "C" void kernel_launch(void* const* d_in, const int* in_sizes, int n_in,
                              void* d_out, int out_size)
{
    const float* x = (const float*)d_in[0];
    float* out = (float*)d_out;

    const int rows = in_sizes[0] / N_SAMP;  // 128*8 = 1024
    const size_t smem = (size_t)(E_PAD + Y1_PAD) * sizeof(float);  // ~33.7 KB

    dim3 grid(N_CHUNKS, rows);
    filtfilt_kernel<<<grid, T_THREADS, smem>>>(x, out);
}

// round 5
// speedup vs baseline: 1.5759x; 1.5759x over previous
#include <cuda_runtime.h>

// filtfilt, 2nd-order Butterworth, odd extension padlen=9, zero initial state.
// Linear filter => max|x| normalization cancels exactly and is omitted.
// Parallelized via warm-up truncation: |pole| = 0.577, 0.577^24 = 1.9e-6 << 1e-3.
// R2: state-space recurrence (1-FMA critical path on z1) + 128 thr/block.

#define T_THREADS 128
#define CHUNK_C   32
#define S_OUT     (T_THREADS * CHUNK_C)   // 4096 outputs per block
#define W_WARM    24
#define PADLEN    9
#define N_SAMP    32768
#define E_LEN     (N_SAMP + 2 * PADLEN)   // 32786
#define N_CHUNKS  (N_SAMP / S_OUT)        // 8

#define E_MAX   (S_OUT + 2 * W_WARM)              // 4144
#define Y1_MAX  (S_OUT + W_WARM)                  // 4120
#define E_PAD   (E_MAX + (E_MAX >> 5) + 1)
#define Y1_PAD  (Y1_MAX + (Y1_MAX >> 5) + 1)

// per-thread smem stride is CHUNK_C=32 -> pad every 32 floats (stride 33, odd)
__device__ __forceinline__ int padidx(int i) { return i + (i >> 5); }

__global__ void __launch_bounds__(T_THREADS)
filtfilt_kernel(const float* __restrict__ x, float* __restrict__ out)
{
    extern __shared__ float sm[];
    float* e_s  = sm;          // extended input; reused as y2 staging
    float* y1_s = sm + E_PAD;  // forward-pass output

    const int row   = blockIdx.y;
    const int chunk = blockIdx.x;
    const int tid   = threadIdx.x;

    const float* xr   = x   + (long)row * N_SAMP;
    float*       outr = out + (long)row * N_SAMP;

    const int t0   = PADLEN + chunk * S_OUT;
    const int e_lo = max(0, t0 - W_WARM);
    const int e_hi = min(t0 + S_OUT + W_WARM, E_LEN);
    const int e_cnt = e_hi - e_lo;

    // filter coefficients (a0 = 1)
    const float b0 = 0.0976310729378175f;
    const float b1 = 0.195262145875635f;
    const float b2 = 0.0976310729378175f;
    const float a1 = -0.9428090415820634f;
    const float a2 = 0.33333333333333337f;
    // state-space form: z1' = c1*x + d1*z1 + z2 ; z2' = c2*x + d2*z1 ; y = b0*x + z1
    const float c1 = b1 - a1 * b0;
    const float c2 = b2 - a2 * b0;
    const float d1 = -a1;
    const float d2 = -a2;

    // ---- stage extended signal (odd extension on the fly), coalesced ----
    for (int i = tid; i < e_cnt; i += T_THREADS) {
        int t = e_lo + i;
        float v;
        if (t >= PADLEN) {
            if (t < PADLEN + N_SAMP)
                v = xr[t - PADLEN];
            else
                v = 2.0f * xr[N_SAMP - 1] - xr[2 * N_SAMP + PADLEN - 2 - t];
        } else {
            v = 2.0f * xr[0] - xr[PADLEN - t];
        }
        e_s[padidx(i)] = v;
    }
    __syncthreads();

    // ---- forward IIR, per-thread chunk with warm-up ----
    {
        const int u      = t0 + tid * CHUNK_C;
        const int wstart = max(e_lo, u - W_WARM);
        int kend = u + CHUNK_C;
        if (tid == T_THREADS - 1)
            kend = min(u + CHUNK_C + W_WARM, E_LEN);

        float z1 = 0.0f, z2 = 0.0f;
        #pragma unroll 4
        for (int t = wstart; t < u; ++t) {          // warm-up: no y needed
            float ev = e_s[padidx(t - e_lo)];
            float nz1 = fmaf(d1, z1, fmaf(c1, ev, z2));
            z2 = fmaf(d2, z1, c2 * ev);
            z1 = nz1;
        }
        #pragma unroll 8
        for (int t = u; t < kend; ++t) {            // kept region
            float ev = e_s[padidx(t - e_lo)];
            y1_s[padidx(t - t0)] = fmaf(b0, ev, z1);
            float nz1 = fmaf(d1, z1, fmaf(c1, ev, z2));
            z2 = fmaf(d2, z1, c2 * ev);
            z1 = nz1;
        }
    }
    __syncthreads();

    // ---- backward IIR on y1 ----
    {
        const int u      = t0 + tid * CHUNK_C;
        const int bstart = min(u + CHUNK_C + W_WARM, E_LEN) - 1;  // exact state at true end

        float z1 = 0.0f, z2 = 0.0f;
        #pragma unroll 4
        for (int t = bstart; t >= u + CHUNK_C; --t) {  // warm-up
            float v = y1_s[padidx(t - t0)];
            float nz1 = fmaf(d1, z1, fmaf(c1, v, z2));
            z2 = fmaf(d2, z1, c2 * v);
            z1 = nz1;
        }
        #pragma unroll 8
        for (int t = u + CHUNK_C - 1; t >= u; --t) {   // kept -> stage into e_s
            float v = y1_s[padidx(t - t0)];
            e_s[padidx(t - t0)] = fmaf(b0, v, z1);
            float nz1 = fmaf(d1, z1, fmaf(c1, v, z2));
            z2 = fmaf(d2, z1, c2 * v);
            z1 = nz1;
        }
    }
    __syncthreads();

    // ---- coalesced vectorized writeout ----
    {
        float4* o4 = (float4*)(outr + (t0 - PADLEN));
        for (int i = tid; i < S_OUT / 4; i += T_THREADS) {
            float4 v;
            v.x = e_s[padidx(4 * i + 0)];
            v.y = e_s[padidx(4 * i + 1)];
            v.z = e_s[padidx(4 * i + 2)];
            v.w = e_s[padidx(4 * i + 3)];
            o4[i] = v;
        }
    }
}

extern "C" void kernel_launch(void* const* d_in, const int* in_sizes, int n_in,
                              void* d_out, int out_size)
{
    const float* x = (const float*)d_in[0];
    float* out = (float*)d_out;

    const int rows = in_sizes[0] / N_SAMP;  // 1024
    const size_t smem = (size_t)(E_PAD + Y1_PAD) * sizeof(float);  // ~34 KB

    dim3 grid(N_CHUNKS, rows);
    filtfilt_kernel<<<grid, T_THREADS, smem>>>(x, out);
}